// round 3
// baseline (speedup 1.0000x reference)
#include <cuda_runtime.h>
#include <cstdint>
#include <cstddef>

#define BATCH 4096
#define SEQ   60
#define INP   13
#define HID   128
#define GATES 512
#define MROWS (BATCH*SEQ)
#define BT    32
#define HPAD  34

__device__ float g_xp[(size_t)2 * MROWS * GATES];
__device__ float g_y0[(size_t)MROWS * 256];
__device__ float g_y1[(size_t)MROWS * 256];
__device__ float g_whhT[6 * HID * GATES];
__device__ float g_wihT[4 * 256 * GATES];
__device__ float g_w0T [2 * INP * GATES];

__device__ __forceinline__ unsigned long long pack_dup(float x) {
    unsigned long long r; asm("mov.b64 %0, {%1, %1};" : "=l"(r) : "f"(x)); return r;
}
__device__ __forceinline__ unsigned long long pack2(float x, float y) {
    unsigned long long r; asm("mov.b64 %0, {%1, %2};" : "=l"(r) : "f"(x), "f"(y)); return r;
}
__device__ __forceinline__ void unpack2(unsigned long long v, float& x, float& y) {
    asm("mov.b64 {%0, %1}, %2;" : "=f"(x), "=f"(y) : "l"(v));
}
__device__ __forceinline__ void fma2(unsigned long long& d, unsigned long long a, unsigned long long b) {
    asm("fma.rn.f32x2 %0, %1, %2, %3;" : "=l"(d) : "l"(a), "l"(b), "l"(d));
}
__device__ __forceinline__ float sigf(float x) { return __fdividef(1.f, 1.f + __expf(-x)); }
__device__ __forceinline__ float tanhf_(float x) {
    float ax = fabsf(x); float e = __expf(-2.f * ax);
    return copysignf(__fdividef(1.f - e, 1.f + e), x);
}

__global__ void transpose_kernel(float* __restrict__ dst, const float* __restrict__ src,
                                 int R, int C) {
    int i = blockIdx.x * 256 + threadIdx.x;
    if (i < R * C) { int c = i / R, r = i % R; dst[i] = src[r * C + c]; }
}

// one bi-dir layer's recurrence; dir = blockIdx.y; 32 batch rows per CTA
__global__ __launch_bounds__(256, 2)
void lstm_rec_kernel(const float* __restrict__ xp, const float* __restrict__ x,
                     const float* __restrict__ w0T,
                     const float* __restrict__ bihF, const float* __restrict__ bhhF,
                     const float* __restrict__ bihB, const float* __restrict__ bhhB,
                     const float* __restrict__ whhTF, const float* __restrict__ whhTB,
                     float* __restrict__ y, int is_layer0)
{
    const int dir = blockIdx.y;
    const int b0  = blockIdx.x * BT;
    const int tid = threadIdx.x;
    const int bg  = tid >> 6;
    const int hc0 = (tid & 63) * 2;
    const float* whhT = dir ? whhTB : whhTF;

    __shared__ unsigned long long h2[128 * HPAD];
    __shared__ float xsm[BT][16];

    for (int i = tid; i < 128 * HPAD; i += 256) h2[i] = 0ull;

    unsigned long long c2[8];
#pragma unroll
    for (int i = 0; i < 8; i++) c2[i] = 0ull;

    unsigned long long bias2[4];
    const float* w0 = w0T + (size_t)dir * INP * GATES;
    if (is_layer0) {
        const float* bi = dir ? bihB : bihF;
        const float* bh = dir ? bhhB : bhhF;
#pragma unroll
        for (int g = 0; g < 4; g++) {
            int j = g * 128 + hc0;
            bias2[g] = pack2(bi[j] + bh[j], bi[j + 1] + bh[j + 1]);
        }
        int t0 = dir ? (SEQ - 1) : 0;
        for (int i = tid; i < BT * INP; i += 256) {
            int b = i / INP, q = i % INP;
            xsm[b][q] = x[((size_t)(b0 + b) * SEQ + t0) * INP + q];
        }
    }
    __syncthreads();

    const size_t xpdir = (size_t)dir * MROWS * GATES;

    for (int s = 0; s < SEQ; ++s) {
        const int t = dir ? (SEQ - 1 - s) : s;
        unsigned long long acc[8][4];

        if (is_layer0) {
#pragma unroll
            for (int bb = 0; bb < 8; ++bb)
#pragma unroll
                for (int g = 0; g < 4; ++g) acc[bb][g] = bias2[g];
#pragma unroll
            for (int q = 0; q < INP; ++q) {
                const unsigned long long* wq =
                    reinterpret_cast<const unsigned long long*>(w0 + (size_t)q * GATES + hc0);
                unsigned long long w0v = wq[0], w1v = wq[64], w2v = wq[128], w3v = wq[192];
#pragma unroll
                for (int bb = 0; bb < 8; ++bb) {
                    unsigned long long xd = pack_dup(xsm[bg * 8 + bb][q]);
                    fma2(acc[bb][0], xd, w0v); fma2(acc[bb][1], xd, w1v);
                    fma2(acc[bb][2], xd, w2v); fma2(acc[bb][3], xd, w3v);
                }
            }
        } else {
#pragma unroll
            for (int bb = 0; bb < 8; ++bb) {
                const float* xpp = xp + xpdir + ((size_t)(b0 + bg * 8 + bb) * SEQ + t) * GATES + hc0;
#pragma unroll
                for (int g = 0; g < 4; ++g)
                    acc[bb][g] = *reinterpret_cast<const unsigned long long*>(xpp + g * 128);
            }
        }

        const float* wbase = whhT + hc0;
#pragma unroll 4
        for (int k = 0; k < HID; ++k) {
            const unsigned long long* wr =
                reinterpret_cast<const unsigned long long*>(wbase + (size_t)k * GATES);
            unsigned long long wv0 = wr[0], wv1 = wr[64], wv2 = wr[128], wv3 = wr[192];
            const unsigned long long* hrow = &h2[k * HPAD + (bg << 3)];
#pragma unroll
            for (int bb = 0; bb < 8; ++bb) {
                unsigned long long hv = hrow[bb];
                fma2(acc[bb][0], hv, wv0); fma2(acc[bb][1], hv, wv1);
                fma2(acc[bb][2], hv, wv2); fma2(acc[bb][3], hv, wv3);
            }
        }
        __syncthreads();

#pragma unroll
        for (int bb = 0; bb < 8; ++bb) {
            float i0, i1, f0, f1, gg0, gg1, o0, o1, cc0, cc1;
            unpack2(acc[bb][0], i0, i1); unpack2(acc[bb][1], f0, f1);
            unpack2(acc[bb][2], gg0, gg1); unpack2(acc[bb][3], o0, o1);
            unpack2(c2[bb], cc0, cc1);
            cc0 = sigf(f0) * cc0 + sigf(i0) * tanhf_(gg0);
            cc1 = sigf(f1) * cc1 + sigf(i1) * tanhf_(gg1);
            float h0 = sigf(o0) * tanhf_(cc0);
            float h1 = sigf(o1) * tanhf_(cc1);
            c2[bb] = pack2(cc0, cc1);
            int b = bg * 8 + bb;
            h2[(hc0)     * HPAD + b] = pack_dup(h0);
            h2[(hc0 + 1) * HPAD + b] = pack_dup(h1);
            *reinterpret_cast<float2*>(
                &y[((size_t)(b0 + b) * SEQ + t) * 256 + dir * 128 + hc0]) = make_float2(h0, h1);
        }
        if (is_layer0 && s < SEQ - 1) {
            int tn = dir ? (SEQ - 2 - s) : (s + 1);
            for (int i = tid; i < BT * INP; i += 256) {
                int b = i / INP, q = i % INP;
                xsm[b][q] = x[((size_t)(b0 + b) * SEQ + tn) * INP + q];
            }
        }
        __syncthreads();
    }
}

// xp[dir][m][n] = A[m][0:256] . Wt[0:256][n] + bih[n] + bhh[n]
__global__ __launch_bounds__(256, 2)
void gemm_xp_kernel(const float* __restrict__ A,
                    const float* __restrict__ WtF, const float* __restrict__ WtB,
                    const float* __restrict__ bihF, const float* __restrict__ bhhF,
                    const float* __restrict__ bihB, const float* __restrict__ bhhB,
                    float* __restrict__ xp)
{
    const int dir = blockIdx.z;
    const float* Wt  = dir ? WtB  : WtF;
    const float* bih = dir ? bihB : bihF;
    const float* bhh = dir ? bhhB : bhhF;
    const int m0 = blockIdx.x * 128;
    const int n0 = blockIdx.y * 128;
    const int tid = threadIdx.x;

    __shared__ float As[16][128];
    __shared__ float Bs[16][128];

    const int ty = tid >> 4, tx = tid & 15;
    const int la_r = tid >> 2, la_c = (tid & 3) * 4;
    const int lb_r = tid >> 5, lb_c = (tid & 31) * 4;

    unsigned long long acc[8][4];
#pragma unroll
    for (int i = 0; i < 8; i++)
#pragma unroll
        for (int j = 0; j < 4; j++) acc[i][j] = 0ull;

    for (int kc = 0; kc < 256; kc += 16) {
#pragma unroll
        for (int rr = 0; rr < 2; ++rr) {
            int r = la_r + rr * 64;
            float4 v = *reinterpret_cast<const float4*>(&A[(size_t)(m0 + r) * 256 + kc + la_c]);
            As[la_c + 0][r] = v.x; As[la_c + 1][r] = v.y;
            As[la_c + 2][r] = v.z; As[la_c + 3][r] = v.w;
        }
#pragma unroll
        for (int rr = 0; rr < 2; ++rr) {
            int r = lb_r + rr * 8;
            *reinterpret_cast<float4*>(&Bs[r][lb_c]) =
                *reinterpret_cast<const float4*>(&Wt[(size_t)(kc + r) * GATES + n0 + lb_c]);
        }
        __syncthreads();
#pragma unroll
        for (int k = 0; k < 16; ++k) {
            float a[8];
            *reinterpret_cast<float4*>(&a[0]) = *reinterpret_cast<const float4*>(&As[k][ty * 8]);
            *reinterpret_cast<float4*>(&a[4]) = *reinterpret_cast<const float4*>(&As[k][ty * 8 + 4]);
            const unsigned long long* bp = reinterpret_cast<const unsigned long long*>(&Bs[k][tx * 8]);
            unsigned long long bv0 = bp[0], bv1 = bp[1], bv2 = bp[2], bv3 = bp[3];
#pragma unroll
            for (int i = 0; i < 8; ++i) {
                unsigned long long ad = pack_dup(a[i]);
                fma2(acc[i][0], ad, bv0); fma2(acc[i][1], ad, bv1);
                fma2(acc[i][2], ad, bv2); fma2(acc[i][3], ad, bv3);
            }
        }
        __syncthreads();
    }

    const size_t base = (size_t)dir * (size_t)MROWS * GATES;
#pragma unroll
    for (int i = 0; i < 8; ++i) {
        size_t row = base + (size_t)(m0 + ty * 8 + i) * GATES + n0 + tx * 8;
#pragma unroll
        for (int j = 0; j < 4; ++j) {
            float x0, x1; unpack2(acc[i][j], x0, x1);
            int n = n0 + tx * 8 + 2 * j;
            x0 += bih[n] + bhh[n]; x1 += bih[n + 1] + bhh[n + 1];
            *reinterpret_cast<float2*>(&xp[row + 2 * j]) = make_float2(x0, x1);
        }
    }
}

__global__ void final_kernel(const float* __restrict__ y, const float* __restrict__ wout,
                             const float* __restrict__ bout, float* __restrict__ out)
{
    const int b = blockIdx.x;
    const int tid = threadIdx.x;
    const float* yr = y + (size_t)b * 15360;
    float s0 = 0.f, s1 = 0.f;
    for (int j = tid * 4; j < 15360; j += 128 * 4) {
        float4 v = *reinterpret_cast<const float4*>(&yr[j]);
        v.x = fmaxf(v.x, 0.f); v.y = fmaxf(v.y, 0.f);
        v.z = fmaxf(v.z, 0.f); v.w = fmaxf(v.w, 0.f);
        float4 w0 = __ldg(reinterpret_cast<const float4*>(&wout[j]));
        float4 w1 = __ldg(reinterpret_cast<const float4*>(&wout[15360 + j]));
        s0 += v.x * w0.x + v.y * w0.y + v.z * w0.z + v.w * w0.w;
        s1 += v.x * w1.x + v.y * w1.y + v.z * w1.z + v.w * w1.w;
    }
#pragma unroll
    for (int off = 16; off > 0; off >>= 1) {
        s0 += __shfl_down_sync(0xffffffffu, s0, off);
        s1 += __shfl_down_sync(0xffffffffu, s1, off);
    }
    __shared__ float r0[4], r1[4];
    int wid = tid >> 5;
    if ((tid & 31) == 0) { r0[wid] = s0; r1[wid] = s1; }
    __syncthreads();
    if (tid == 0) {
        out[(size_t)b * 2 + 0] = r0[0] + r0[1] + r0[2] + r0[3] + __ldg(&bout[0]);
        out[(size_t)b * 2 + 1] = r1[0] + r1[1] + r1[2] + r1[3] + __ldg(&bout[1]);
    }
}

extern "C" void kernel_launch(void* const* d_in, const int* in_sizes, int n_in,
                              void* d_out, int out_size) {
    const float* x = (const float*)d_in[0];
    const float* w_ih[6]; const float* w_hh[6]; const float* b_ih[6]; const float* b_hh[6];
    for (int i = 0; i < 6; i++) {
        w_ih[i] = (const float*)d_in[1 + 4 * i];
        w_hh[i] = (const float*)d_in[2 + 4 * i];
        b_ih[i] = (const float*)d_in[3 + 4 * i];
        b_hh[i] = (const float*)d_in[4 + 4 * i];
    }
    const float* w_out = (const float*)d_in[25];
    const float* b_out = (const float*)d_in[26];
    float* out = (float*)d_out;

    float *xp, *y0, *y1, *whhT, *wihT, *w0T;
    cudaGetSymbolAddress((void**)&xp,   g_xp);
    cudaGetSymbolAddress((void**)&y0,   g_y0);
    cudaGetSymbolAddress((void**)&y1,   g_y1);
    cudaGetSymbolAddress((void**)&whhT, g_whhT);
    cudaGetSymbolAddress((void**)&wihT, g_wihT);
    cudaGetSymbolAddress((void**)&w0T,  g_w0T);

    for (int i = 0; i < 6; i++)
        transpose_kernel<<<(GATES * HID + 255) / 256, 256>>>(whhT + (size_t)i * HID * GATES,
                                                             w_hh[i], GATES, HID);
    for (int i = 0; i < 4; i++)
        transpose_kernel<<<(GATES * 256 + 255) / 256, 256>>>(wihT + (size_t)i * 256 * GATES,
                                                             w_ih[2 + i], GATES, 256);
    for (int i = 0; i < 2; i++)
        transpose_kernel<<<(GATES * INP + 255) / 256, 256>>>(w0T + (size_t)i * INP * GATES,
                                                             w_ih[i], GATES, INP);

    dim3 rgrid(BATCH / BT, 2);
    dim3 ggrid(MROWS / 128, GATES / 128, 2);

    // layer 0 (input projection fused)
    lstm_rec_kernel<<<rgrid, 256>>>(nullptr, x, w0T,
                                    b_ih[0], b_hh[0], b_ih[1], b_hh[1],
                                    whhT + 0 * (size_t)HID * GATES, whhT + 1 * (size_t)HID * GATES,
                                    y0, 1);
    // layer 1
    gemm_xp_kernel<<<ggrid, 256>>>(y0, wihT + 0 * (size_t)256 * GATES, wihT + 1 * (size_t)256 * GATES,
                                   b_ih[2], b_hh[2], b_ih[3], b_hh[3], xp);
    lstm_rec_kernel<<<rgrid, 256>>>(xp, nullptr, nullptr,
                                    b_ih[2], b_hh[2], b_ih[3], b_hh[3],
                                    whhT + 2 * (size_t)HID * GATES, whhT + 3 * (size_t)HID * GATES,
                                    y1, 0);
    // layer 2
    gemm_xp_kernel<<<ggrid, 256>>>(y1, wihT + 2 * (size_t)256 * GATES, wihT + 3 * (size_t)256 * GATES,
                                   b_ih[4], b_hh[4], b_ih[5], b_hh[5], xp);
    lstm_rec_kernel<<<rgrid, 256>>>(xp, nullptr, nullptr,
                                    b_ih[4], b_hh[4], b_ih[5], b_hh[5],
                                    whhT + 4 * (size_t)HID * GATES, whhT + 5 * (size_t)HID * GATES,
                                    y0, 0);
    // head
    final_kernel<<<BATCH, 128>>>(y0, w_out, b_out, out);
}